// round 16
// baseline (speedup 1.0000x reference)
#include <cuda_runtime.h>
#include <cstdint>
#include <math.h>

#define B_ 64
#define S_ 256
#define H_ 1024
#define G_ 4096
#define NROW (S_*B_)
#define NCTA 128

// ---------------- static scratch ----------------
__device__ float g_x  [NROW*H_];         // embedded, tf32-rounded [S,B,H]
__device__ float g_h1 [NROW*H_];         // layer-1 h seq, rounded [S,B,H]
__device__ float g_xg [(size_t)NROW*G_]; // gate preacts [S,B,4H]
__device__ float g_wxr[2*H_*G_];         // rounded Wx
__device__ float g_whr[2*H_*G_];         // rounded Wh
// h state, double buffered, FRAGMENT-READY layout:
// value h[b][k] stored at b*1024 + (k>>4)*16 + (k&3)*4 + ((k>>2)&3)
__device__ float g_hbuf[2][B_*H_];
__device__ unsigned g_flags[NCTA*32];    // per-CTA progress flags, 128B stride

// ---------------- helpers ----------------
__device__ __forceinline__ unsigned f2tf(float v) {
    unsigned r; asm("cvt.rna.tf32.f32 %0, %1;" : "=r"(r) : "f"(v)); return r;
}
__device__ __forceinline__ void mma_tf32(float* c, const unsigned* a, const unsigned* b) {
    asm volatile(
        "mma.sync.aligned.m16n8k8.row.col.f32.tf32.tf32.f32 "
        "{%0,%1,%2,%3}, {%4,%5,%6,%7}, {%8,%9}, {%0,%1,%2,%3};"
        : "+f"(c[0]), "+f"(c[1]), "+f"(c[2]), "+f"(c[3])
        : "r"(a[0]), "r"(a[1]), "r"(a[2]), "r"(a[3]), "r"(b[0]), "r"(b[1]));
}
__device__ __forceinline__ void cpa16(void* s, const void* g) {
    unsigned ss = (unsigned)__cvta_generic_to_shared(s);
    asm volatile("cp.async.cg.shared.global [%0], [%1], 16;" :: "r"(ss), "l"(g));
}
__device__ __forceinline__ void cpa_commit() { asm volatile("cp.async.commit_group;"); }
template<int N> __device__ __forceinline__ void cpa_wait() {
    asm volatile("cp.async.wait_group %0;" :: "n"(N));
}
__device__ __forceinline__ float sigm(float x) { return 1.f / (1.f + __expf(-x)); }

// ---------------- prep: round both weight tensors + reset flags ------
__global__ void round_both(const float* __restrict__ wx, const float* __restrict__ wh) {
    if (blockIdx.x == 0 && threadIdx.x < NCTA) g_flags[threadIdx.x * 32] = 0;
    int half = blockIdx.x >> 13;                    // 0: Wx, 1: Wh
    size_t i = (size_t)(blockIdx.x & 8191) * 256 + threadIdx.x;  // float4 index
    const float* src = half ? wh : wx;
    float4 v = ((const float4*)src)[i];
    float4 o;
    o.x = __uint_as_float(f2tf(v.x)); o.y = __uint_as_float(f2tf(v.y));
    o.z = __uint_as_float(f2tf(v.z)); o.w = __uint_as_float(f2tf(v.w));
    ((float4*)(half ? g_whr : g_wxr))[i] = o;
}

// ---------------- embed ----------------
__global__ void embed_kernel(const int* __restrict__ inputs, const float* __restrict__ emb) {
    int rid = blockIdx.x;                  // s*64 + b
    int b = rid & 63, s = rid >> 6;
    int tok = inputs[b * S_ + s];
    float4 v = ((const float4*)(emb + (size_t)tok * H_))[threadIdx.x];
    float4 o;
    o.x = __uint_as_float(f2tf(v.x)); o.y = __uint_as_float(f2tf(v.y));
    o.z = __uint_as_float(f2tf(v.z)); o.w = __uint_as_float(f2tf(v.w));
    ((float4*)(g_x + (size_t)rid * H_))[threadIdx.x] = o;
}

// ---------------- xg GEMM: [16384,1024] @ [1024,4096] + bias ----------------
#define GBM 128
#define GBN 128
#define GBK 32
#define ALD 36
#define BLD 136
#define ABUF (GBM*ALD)
#define BBUF (GBK*BLD)
#define GEMM_SMEM ((2*(ABUF+BBUF))*4)

__global__ void __launch_bounds__(256, 2) gemm_xg(int layer, const float* __restrict__ bias) {
    extern __shared__ float sm[];
    float* As = sm;
    float* Bs = sm + 2 * ABUF;
    const float* A  = layer ? g_h1 : g_x;
    const float* Bw = g_wxr + (size_t)layer * H_ * G_;
    int tid = threadIdx.x;
    int bn = blockIdx.x, bm = blockIdx.y;
    const float* Ab = A + (size_t)bm * GBM * H_;
    const float* Bb = Bw + bn * GBN;
    int wid = tid >> 5, lane = tid & 31, g = lane >> 2, tg = lane & 3;
    int wm = (wid & 1) * 64, wn = (wid >> 1) * 32;

    float acc[4][4][4];
#pragma unroll
    for (int a = 0; a < 4; a++)
#pragma unroll
        for (int b = 0; b < 4; b++)
#pragma unroll
            for (int c = 0; c < 4; c++) acc[a][b][c] = 0.f;

    auto stage = [&](int it) {
        float* Ad = As + (it & 1) * ABUF;
        float* Bd = Bs + (it & 1) * BBUF;
        int k0 = it * GBK;
#pragma unroll
        for (int q = 0; q < 4; q++) {
            int idx = tid + q * 256; int r = idx >> 3, c4 = (idx & 7) << 2;
            cpa16(Ad + r * ALD + c4, Ab + (size_t)r * H_ + k0 + c4);
        }
#pragma unroll
        for (int q = 0; q < 4; q++) {
            int idx = tid + q * 256; int r = idx >> 5, c4 = (idx & 31) << 2;
            cpa16(Bd + r * BLD + c4, Bb + (size_t)(k0 + r) * G_ + c4);
        }
        cpa_commit();
    };

    stage(0);
    for (int it = 0; it < H_ / GBK; it++) {
        if (it + 1 < H_ / GBK) { stage(it + 1); cpa_wait<1>(); }
        else cpa_wait<0>();
        __syncthreads();
        const float* uA = As + (it & 1) * ABUF;
        const float* uB = Bs + (it & 1) * BBUF;
#pragma unroll
        for (int kk = 0; kk < 4; kk++) {
            unsigned af[4][4];
#pragma unroll
            for (int mt = 0; mt < 4; mt++) {
                int r0 = wm + mt * 16 + g; int k = kk * 8 + tg;
                af[mt][0] = __float_as_uint(uA[r0 * ALD + k]);
                af[mt][1] = __float_as_uint(uA[(r0 + 8) * ALD + k]);
                af[mt][2] = __float_as_uint(uA[r0 * ALD + k + 4]);
                af[mt][3] = __float_as_uint(uA[(r0 + 8) * ALD + k + 4]);
            }
            unsigned bf[4][2];
#pragma unroll
            for (int nt = 0; nt < 4; nt++) {
                int n = wn + nt * 8 + g;
                bf[nt][0] = __float_as_uint(uB[(kk * 8 + tg) * BLD + n]);
                bf[nt][1] = __float_as_uint(uB[(kk * 8 + tg + 4) * BLD + n]);
            }
#pragma unroll
            for (int mt = 0; mt < 4; mt++)
#pragma unroll
                for (int nt = 0; nt < 4; nt++) mma_tf32(acc[mt][nt], af[mt], bf[nt]);
        }
        __syncthreads();
    }

#pragma unroll
    for (int mt = 0; mt < 4; mt++)
#pragma unroll
        for (int nt = 0; nt < 4; nt++) {
            int row = bm * GBM + wm + mt * 16 + g;
            int col = bn * GBN + wn + nt * 8 + tg * 2;
            float b0 = bias[col], b1 = bias[col + 1];
            float* o = g_xg + (size_t)row * G_ + col;
            o[0] = acc[mt][nt][0] + b0; o[1] = acc[mt][nt][1] + b1;
            o = g_xg + (size_t)(row + 8) * G_ + col;
            o[0] = acc[mt][nt][2] + b0; o[1] = acc[mt][nt][3] + b1;
        }
}

// ---------------- persistent recurrent kernel ----------------
// smem (floats): sA[256][132] thread-private A fragments @0 (33792),
// hstage 2x8192 @33792 (16384; reused as rbuf during reduce), sXg 2x2048 @50176.
// Inter-CTA sync: NO global barrier. Warp w's staging chunk t reads h units
// produced by CTAs 16w+2t and 16w+2t+1 only -> poll exactly those 2 flags.
#define SA_F 33792
#define STGB_F 8192
#define SXG_F 50176
#define PS_SMEM (54272*4)

#define OUT_CS 16777216
#define OUT_HS (16777216 + 2 * B_ * H_)
#define LSTRIDE (B_ * H_)

__global__ void __launch_bounds__(256) lstm_pers(int layer,
                                                 const int* __restrict__ lengths,
                                                 float* __restrict__ out) {
    extern __shared__ float sm[];
    float* sA   = sm;
    float* sStg = sm + SA_F;
    float* sXg  = sm + SXG_F;
    float4* rbuf4 = (float4*)sStg;   // aliases staging (dead during reduce)

    const float* whL = g_whr + (size_t)layer * H_ * G_;
    int tid = threadIdx.x, w = tid >> 5, lane = tid & 31, g = lane >> 2, tg = lane & 3;
    int u0 = blockIdx.x * 8;
    unsigned tbase = (unsigned)(layer * S_);

    auto prefetch_xg = [&](int s) {
        const float* xgS = g_xg + (size_t)s * 64 * G_;
        float* dst = sXg + (s & 1) * 2048;
#pragma unroll
        for (int r = 0; r < 2; r++) {
            int op = tid + (r << 8);
            int gb = op >> 1, half = op & 1;
            int gate = gb >> 6, b = gb & 63;
            cpa16(dst + gate * 512 + b * 8 + half * 4,
                  xgS + (size_t)b * G_ + (gate << 10) + u0 + half * 4);
        }
        cpa_commit();
    };
    prefetch_xg(0);

    // ---- one-time: fill thread-private A fragments ----
    {
        float* myA = sA + tid * 132;
#pragma unroll
        for (int t = 0; t < 8; t++)
#pragma unroll
            for (int kc = 0; kc < 2; kc++) {
                int kb = w * 128 + t * 16 + kc * 8;
                const float* r0 = whL + (size_t)(kb + tg) * G_ + u0 + g;
                const float* r4 = whL + (size_t)(kb + tg + 4) * G_ + u0 + g;
                float* d = myA + t * 16 + kc * 8;
                d[0] = r0[0];    d[1] = r0[1024]; d[2] = r4[0];    d[3] = r4[1024];
                d[4] = r0[2048]; d[5] = r0[3072]; d[6] = r4[2048]; d[7] = r4[3072];
            }
    }

    float creg[2] = {0.f, 0.f}, hreg[2] = {0.f, 0.f};
    int lenr[2];
#pragma unroll
    for (int hh = 0; hh < 2; hh++) lenr[hh] = lengths[w * 8 + tg * 2 + hh];

    int u = u0 + g;
    int hoff = (u >> 4) * 16 + (u & 3) * 4 + ((u >> 2) & 3);  // fragment-ready write slot
    const float4* myA4 = (const float4*)(sA + tid * 132);

    __syncthreads();

    for (int s = 0; s < S_; s++) {
        const float* hin = g_hbuf[s & 1];
        float* hout = g_hbuf[(s + 1) & 1];

        float acc[2][8][4];
#pragma unroll
        for (int mt = 0; mt < 2; mt++)
#pragma unroll
            for (int nt = 0; nt < 8; nt++)
#pragma unroll
                for (int j = 0; j < 4; j++) acc[mt][nt][j] = 0.f;

        if (s > 0) {
            unsigned tgt = tbase + (unsigned)s;
            // poll the 2 producer CTAs of chunk t (units 16w+2t, 16w+2t+1)
            auto wait_pair = [&](int t) {
                if (lane < 2) {
                    const unsigned* p = (const unsigned*)&g_flags[(16 * w + 2 * t + lane) * 32];
                    unsigned v;
                    do {
                        asm volatile("ld.acquire.gpu.global.u32 %0, [%1];"
                                     : "=r"(v) : "l"(p) : "memory");
                    } while (v < tgt);
                }
                __syncwarp();
            };
            auto stagec = [&](int t, int buf) {
                float* d = sStg + buf * STGB_F + w * 1024;
                const float* src = hin + (w * 8 + t) * 16;
#pragma unroll
                for (int r = 0; r < 8; r++) {
                    int op = lane + (r << 5);
                    int b = op >> 2, grp = op & 3;
                    cpa16(d + b * 16 + grp * 4, src + (size_t)b * 1024 + grp * 4);
                }
                cpa_commit();
            };
            wait_pair(0);
            stagec(0, 0);
#pragma unroll 2
            for (int t = 0; t < 8; t++) {
                if (t < 7) { wait_pair(t + 1); stagec(t + 1, (t + 1) & 1); cpa_wait<1>(); }
                else cpa_wait<0>();
                __syncwarp();
                // A fragments: 4 transient LDS.128, conflict-free (stride 33 f4)
                float4 va0 = myA4[t * 4 + 0];
                float4 va1 = myA4[t * 4 + 1];
                float4 va2 = myA4[t * 4 + 2];
                float4 va3 = myA4[t * 4 + 3];
                unsigned A0a[4] = {__float_as_uint(va0.x), __float_as_uint(va0.y),
                                   __float_as_uint(va0.z), __float_as_uint(va0.w)};
                unsigned A0b[4] = {__float_as_uint(va1.x), __float_as_uint(va1.y),
                                   __float_as_uint(va1.z), __float_as_uint(va1.w)};
                unsigned A1a[4] = {__float_as_uint(va2.x), __float_as_uint(va2.y),
                                   __float_as_uint(va2.z), __float_as_uint(va2.w)};
                unsigned A1b[4] = {__float_as_uint(va3.x), __float_as_uint(va3.y),
                                   __float_as_uint(va3.z), __float_as_uint(va3.w)};
                const float4* hb4 = (const float4*)(sStg + (t & 1) * STGB_F + w * 1024);
#pragma unroll
                for (int nt = 0; nt < 8; nt++) {
                    float4 bv = hb4[(nt * 8 + g) * 4 + tg];
                    unsigned b0[2] = {__float_as_uint(bv.x), __float_as_uint(bv.y)};
                    unsigned b1[2] = {__float_as_uint(bv.z), __float_as_uint(bv.w)};
                    mma_tf32(acc[0][nt], A0a, b0);
                    mma_tf32(acc[1][nt], A0b, b0);
                    mma_tf32(acc[0][nt], A1a, b1);
                    mma_tf32(acc[1][nt], A1b, b1);
                }
            }
        } else {
            cpa_wait<0>();
        }

        // prefetch next step's xg slice (independent of h)
        if (s + 1 < S_) prefetch_xg(s + 1);

        // ---- cross-warp reduce: rbuf4[src*512 + f*32 + lane], conflict-free ----
        __syncthreads();
#pragma unroll
        for (int mt = 0; mt < 2; mt++)
#pragma unroll
            for (int nt = 0; nt < 8; nt++)
                rbuf4[w * 512 + (mt * 8 + nt) * 32 + lane] =
                    make_float4(acc[mt][nt][0], acc[mt][nt][1], acc[mt][nt][2], acc[mt][nt][3]);
        __syncthreads();
        float fin[2][4];
#pragma unroll
        for (int mt = 0; mt < 2; mt++)
#pragma unroll
            for (int j = 0; j < 4; j++) fin[mt][j] = 0.f;
#pragma unroll
        for (int src = 0; src < 8; src++) {
            float4 v0 = rbuf4[src * 512 + w * 32 + lane];
            float4 v1 = rbuf4[src * 512 + (8 + w) * 32 + lane];
            fin[0][0] += v0.x; fin[0][1] += v0.y; fin[0][2] += v0.z; fin[0][3] += v0.w;
            fin[1][0] += v1.x; fin[1][1] += v1.y; fin[1][2] += v1.z; fin[1][3] += v1.w;
        }

        // ---- pointwise: critical path = compute + hout store only ----
        const float* xb = sXg + (s & 1) * 2048;
        float cval[2], hval[2];
#pragma unroll
        for (int hh = 0; hh < 2; hh++) {
            int bb = w * 8 + tg * 2 + hh;
            float iv = fin[0][hh]     + xb[bb * 8 + g];
            float fv = fin[0][2 + hh] + xb[512 + bb * 8 + g];
            float gv = fin[1][hh]     + xb[1024 + bb * 8 + g];
            float ov = fin[1][2 + hh] + xb[1536 + bb * 8 + g];
            float cn = sigm(fv) * creg[hh] + sigm(iv) * tanhf(gv);
            float hn = sigm(ov) * tanhf(cn);
            bool m = s < lenr[hh];
            cval[hh] = m ? cn : creg[hh];
            hval[hh] = m ? hn : hreg[hh];
            creg[hh] = cval[hh];
            hreg[hh] = hval[hh];
            hout[bb * H_ + hoff] = __uint_as_float(f2tf(hval[hh]));
        }

        // publish progress: all hout writes done CTA-wide, then release flag
        __syncthreads();
        if (tid == 0) {
            asm volatile("st.release.gpu.global.u32 [%0], %1;"
                         :: "l"((unsigned*)&g_flags[blockIdx.x * 32]),
                            "r"(tbase + (unsigned)s + 1) : "memory");
        }

        // ---- non-critical output writes (off the inter-CTA critical path) ----
#pragma unroll
        for (int hh = 0; hh < 2; hh++) {
            int bb = w * 8 + tg * 2 + hh;
            float hf = hval[hh];
            if (layer == 0) g_h1[((size_t)s * 64 + bb) * H_ + u] = __uint_as_float(f2tf(hf));
            else            out[((size_t)bb * S_ + s) * H_ + u] = hf;
            if (s == S_ - 1) {
                out[OUT_CS + layer * LSTRIDE + bb * H_ + u] = cval[hh];
                out[OUT_HS + layer * LSTRIDE + bb * H_ + u] = hf;
            }
        }
    }
}

// ---------------- launch ----------------
extern "C" void kernel_launch(void* const* d_in, const int* in_sizes, int n_in,
                              void* d_out, int out_size) {
    const int*   inputs  = (const int*)d_in[0];
    const int*   lengths = (const int*)d_in[1];
    const float* emb     = (const float*)d_in[3];
    const float* Wx      = (const float*)d_in[4];
    const float* Wh      = (const float*)d_in[5];
    const float* bias    = (const float*)d_in[6];
    float* out = (float*)d_out;

    cudaFuncSetAttribute(gemm_xg,   cudaFuncAttributeMaxDynamicSharedMemorySize, GEMM_SMEM);
    cudaFuncSetAttribute(lstm_pers, cudaFuncAttributeMaxDynamicSharedMemorySize, PS_SMEM);

    round_both<<<16384, 256>>>(Wx, Wh);
    embed_kernel<<<NROW, 256>>>(inputs, emb);

    for (int l = 0; l < 2; l++) {
        gemm_xg<<<dim3(32, 128), 256, GEMM_SMEM>>>(l, bias + l * G_);
        lstm_pers<<<NCTA, 256, PS_SMEM>>>(l, lengths, out);
    }
}

// round 17
// speedup vs baseline: 1.2018x; 1.2018x over previous
#include <cuda_runtime.h>
#include <cstdint>
#include <math.h>

#define B_ 64
#define S_ 256
#define H_ 1024
#define G_ 4096
#define NROW (S_*B_)
#define NCTA 128

// ---------------- static scratch ----------------
__device__ float g_x  [NROW*H_];         // embedded, tf32-rounded [S,B,H]
__device__ float g_h1 [NROW*H_];         // layer-1 h seq, rounded [S,B,H]
__device__ float g_xg [(size_t)NROW*G_]; // gate preacts [S,B,4H]
__device__ float g_wxr[2*H_*G_];         // rounded Wx
__device__ float g_whr[2*H_*G_];         // rounded Wh
// h state, double buffered, FRAGMENT-READY layout:
// value h[b][k] stored at b*1024 + (k>>4)*16 + (k&3)*4 + ((k>>2)&3)
__device__ float g_hbuf[2][B_*H_];
__device__ unsigned g_flags[NCTA*32];    // per-CTA progress flags, 128B stride

// ---------------- helpers ----------------
__device__ __forceinline__ unsigned f2tf(float v) {
    unsigned r; asm("cvt.rna.tf32.f32 %0, %1;" : "=r"(r) : "f"(v)); return r;
}
__device__ __forceinline__ void mma_tf32(float* c, const unsigned* a, const unsigned* b) {
    asm volatile(
        "mma.sync.aligned.m16n8k8.row.col.f32.tf32.tf32.f32 "
        "{%0,%1,%2,%3}, {%4,%5,%6,%7}, {%8,%9}, {%0,%1,%2,%3};"
        : "+f"(c[0]), "+f"(c[1]), "+f"(c[2]), "+f"(c[3])
        : "r"(a[0]), "r"(a[1]), "r"(a[2]), "r"(a[3]), "r"(b[0]), "r"(b[1]));
}
__device__ __forceinline__ void cpa16(void* s, const void* g) {
    unsigned ss = (unsigned)__cvta_generic_to_shared(s);
    asm volatile("cp.async.cg.shared.global [%0], [%1], 16;" :: "r"(ss), "l"(g));
}
__device__ __forceinline__ void cpa_commit() { asm volatile("cp.async.commit_group;"); }
template<int N> __device__ __forceinline__ void cpa_wait() {
    asm volatile("cp.async.wait_group %0;" :: "n"(N));
}
__device__ __forceinline__ float sigm(float x) { return 1.f / (1.f + __expf(-x)); }

// ---------------- prep: round both weight tensors + reset flags ------
__global__ void round_both(const float* __restrict__ wx, const float* __restrict__ wh) {
    if (blockIdx.x == 0 && threadIdx.x < NCTA) g_flags[threadIdx.x * 32] = 0;
    int half = blockIdx.x >> 13;                    // 0: Wx, 1: Wh
    size_t i = (size_t)(blockIdx.x & 8191) * 256 + threadIdx.x;  // float4 index
    const float* src = half ? wh : wx;
    float4 v = ((const float4*)src)[i];
    float4 o;
    o.x = __uint_as_float(f2tf(v.x)); o.y = __uint_as_float(f2tf(v.y));
    o.z = __uint_as_float(f2tf(v.z)); o.w = __uint_as_float(f2tf(v.w));
    ((float4*)(half ? g_whr : g_wxr))[i] = o;
}

// ---------------- embed ----------------
__global__ void embed_kernel(const int* __restrict__ inputs, const float* __restrict__ emb) {
    int rid = blockIdx.x;                  // s*64 + b
    int b = rid & 63, s = rid >> 6;
    int tok = inputs[b * S_ + s];
    float4 v = ((const float4*)(emb + (size_t)tok * H_))[threadIdx.x];
    float4 o;
    o.x = __uint_as_float(f2tf(v.x)); o.y = __uint_as_float(f2tf(v.y));
    o.z = __uint_as_float(f2tf(v.z)); o.w = __uint_as_float(f2tf(v.w));
    ((float4*)(g_x + (size_t)rid * H_))[threadIdx.x] = o;
}

// ---------------- xg GEMM: [16384,1024] @ [1024,4096] + bias ----------------
#define GBM 128
#define GBN 128
#define GBK 32
#define ALD 36
#define BLD 136
#define ABUF (GBM*ALD)
#define BBUF (GBK*BLD)
#define GEMM_SMEM ((2*(ABUF+BBUF))*4)

__global__ void __launch_bounds__(256, 2) gemm_xg(int layer, const float* __restrict__ bias) {
    extern __shared__ float sm[];
    float* As = sm;
    float* Bs = sm + 2 * ABUF;
    const float* A  = layer ? g_h1 : g_x;
    const float* Bw = g_wxr + (size_t)layer * H_ * G_;
    int tid = threadIdx.x;
    int bn = blockIdx.x, bm = blockIdx.y;
    const float* Ab = A + (size_t)bm * GBM * H_;
    const float* Bb = Bw + bn * GBN;
    int wid = tid >> 5, lane = tid & 31, g = lane >> 2, tg = lane & 3;
    int wm = (wid & 1) * 64, wn = (wid >> 1) * 32;

    float acc[4][4][4];
#pragma unroll
    for (int a = 0; a < 4; a++)
#pragma unroll
        for (int b = 0; b < 4; b++)
#pragma unroll
            for (int c = 0; c < 4; c++) acc[a][b][c] = 0.f;

    auto stage = [&](int it) {
        float* Ad = As + (it & 1) * ABUF;
        float* Bd = Bs + (it & 1) * BBUF;
        int k0 = it * GBK;
#pragma unroll
        for (int q = 0; q < 4; q++) {
            int idx = tid + q * 256; int r = idx >> 3, c4 = (idx & 7) << 2;
            cpa16(Ad + r * ALD + c4, Ab + (size_t)r * H_ + k0 + c4);
        }
#pragma unroll
        for (int q = 0; q < 4; q++) {
            int idx = tid + q * 256; int r = idx >> 5, c4 = (idx & 31) << 2;
            cpa16(Bd + r * BLD + c4, Bb + (size_t)(k0 + r) * G_ + c4);
        }
        cpa_commit();
    };

    stage(0);
    for (int it = 0; it < H_ / GBK; it++) {
        if (it + 1 < H_ / GBK) { stage(it + 1); cpa_wait<1>(); }
        else cpa_wait<0>();
        __syncthreads();
        const float* uA = As + (it & 1) * ABUF;
        const float* uB = Bs + (it & 1) * BBUF;
#pragma unroll
        for (int kk = 0; kk < 4; kk++) {
            unsigned af[4][4];
#pragma unroll
            for (int mt = 0; mt < 4; mt++) {
                int r0 = wm + mt * 16 + g; int k = kk * 8 + tg;
                af[mt][0] = __float_as_uint(uA[r0 * ALD + k]);
                af[mt][1] = __float_as_uint(uA[(r0 + 8) * ALD + k]);
                af[mt][2] = __float_as_uint(uA[r0 * ALD + k + 4]);
                af[mt][3] = __float_as_uint(uA[(r0 + 8) * ALD + k + 4]);
            }
            unsigned bf[4][2];
#pragma unroll
            for (int nt = 0; nt < 4; nt++) {
                int n = wn + nt * 8 + g;
                bf[nt][0] = __float_as_uint(uB[(kk * 8 + tg) * BLD + n]);
                bf[nt][1] = __float_as_uint(uB[(kk * 8 + tg + 4) * BLD + n]);
            }
#pragma unroll
            for (int mt = 0; mt < 4; mt++)
#pragma unroll
                for (int nt = 0; nt < 4; nt++) mma_tf32(acc[mt][nt], af[mt], bf[nt]);
        }
        __syncthreads();
    }

#pragma unroll
    for (int mt = 0; mt < 4; mt++)
#pragma unroll
        for (int nt = 0; nt < 4; nt++) {
            int row = bm * GBM + wm + mt * 16 + g;
            int col = bn * GBN + wn + nt * 8 + tg * 2;
            float b0 = bias[col], b1 = bias[col + 1];
            float* o = g_xg + (size_t)row * G_ + col;
            o[0] = acc[mt][nt][0] + b0; o[1] = acc[mt][nt][1] + b1;
            o = g_xg + (size_t)(row + 8) * G_ + col;
            o[0] = acc[mt][nt][2] + b0; o[1] = acc[mt][nt][3] + b1;
        }
}

// ---------------- persistent recurrent kernel ----------------
// smem (floats): sA[256][132] thread-private A fragments @0 (33792),
// hstage 2x8192 @33792 (16384; reused as rbuf during reduce), sXg 2x2048 @50176.
// Inter-CTA sync: single wait-all barrier per step, SPLIT into post (right
// after critical hout stores) and drain (after non-critical output writes).
#define SA_F 33792
#define STGB_F 8192
#define SXG_F 50176
#define PS_SMEM (54272*4)

#define OUT_CS 16777216
#define OUT_HS (16777216 + 2 * B_ * H_)
#define LSTRIDE (B_ * H_)

__global__ void __launch_bounds__(256) lstm_pers(int layer,
                                                 const int* __restrict__ lengths,
                                                 float* __restrict__ out) {
    extern __shared__ float sm[];
    float* sA   = sm;
    float* sStg = sm + SA_F;
    float* sXg  = sm + SXG_F;
    float4* rbuf4 = (float4*)sStg;   // aliases staging (dead during reduce)

    const float* whL = g_whr + (size_t)layer * H_ * G_;
    int tid = threadIdx.x, w = tid >> 5, lane = tid & 31, g = lane >> 2, tg = lane & 3;
    int u0 = blockIdx.x * 8;
    unsigned tbase = (unsigned)(layer * S_);

    auto prefetch_xg = [&](int s) {
        const float* xgS = g_xg + (size_t)s * 64 * G_;
        float* dst = sXg + (s & 1) * 2048;
#pragma unroll
        for (int r = 0; r < 2; r++) {
            int op = tid + (r << 8);
            int gb = op >> 1, half = op & 1;
            int gate = gb >> 6, b = gb & 63;
            cpa16(dst + gate * 512 + b * 8 + half * 4,
                  xgS + (size_t)b * G_ + (gate << 10) + u0 + half * 4);
        }
        cpa_commit();
    };
    prefetch_xg(0);

    // ---- one-time: fill thread-private A fragments ----
    {
        float* myA = sA + tid * 132;
#pragma unroll
        for (int t = 0; t < 8; t++)
#pragma unroll
            for (int kc = 0; kc < 2; kc++) {
                int kb = w * 128 + t * 16 + kc * 8;
                const float* r0 = whL + (size_t)(kb + tg) * G_ + u0 + g;
                const float* r4 = whL + (size_t)(kb + tg + 4) * G_ + u0 + g;
                float* d = myA + t * 16 + kc * 8;
                d[0] = r0[0];    d[1] = r0[1024]; d[2] = r4[0];    d[3] = r4[1024];
                d[4] = r0[2048]; d[5] = r0[3072]; d[6] = r4[2048]; d[7] = r4[3072];
            }
    }

    float creg[2] = {0.f, 0.f}, hreg[2] = {0.f, 0.f};
    int lenr[2];
#pragma unroll
    for (int hh = 0; hh < 2; hh++) lenr[hh] = lengths[w * 8 + tg * 2 + hh];

    int u = u0 + g;
    int hoff = (u >> 4) * 16 + (u & 3) * 4 + ((u >> 2) & 3);  // fragment-ready write slot
    const float4* myA4 = (const float4*)(sA + tid * 132);

    __syncthreads();

    for (int s = 0; s < S_; s++) {
        const float* hin = g_hbuf[s & 1];
        float* hout = g_hbuf[(s + 1) & 1];

        float acc[2][8][4];
#pragma unroll
        for (int mt = 0; mt < 2; mt++)
#pragma unroll
            for (int nt = 0; nt < 8; nt++)
#pragma unroll
                for (int j = 0; j < 4; j++) acc[mt][nt][j] = 0.f;

        if (s > 0) {
            auto stagec = [&](int t, int buf) {
                float* d = sStg + buf * STGB_F + w * 1024;
                const float* src = hin + (w * 8 + t) * 16;
#pragma unroll
                for (int r = 0; r < 8; r++) {
                    int op = lane + (r << 5);
                    int b = op >> 2, grp = op & 3;
                    cpa16(d + b * 16 + grp * 4, src + (size_t)b * 1024 + grp * 4);
                }
                cpa_commit();
            };
            stagec(0, 0);
#pragma unroll 2
            for (int t = 0; t < 8; t++) {
                if (t < 7) { stagec(t + 1, (t + 1) & 1); cpa_wait<1>(); }
                else cpa_wait<0>();
                __syncwarp();
                // A fragments: 4 transient LDS.128, conflict-free (stride 33 f4)
                float4 va0 = myA4[t * 4 + 0];
                float4 va1 = myA4[t * 4 + 1];
                float4 va2 = myA4[t * 4 + 2];
                float4 va3 = myA4[t * 4 + 3];
                unsigned A0a[4] = {__float_as_uint(va0.x), __float_as_uint(va0.y),
                                   __float_as_uint(va0.z), __float_as_uint(va0.w)};
                unsigned A0b[4] = {__float_as_uint(va1.x), __float_as_uint(va1.y),
                                   __float_as_uint(va1.z), __float_as_uint(va1.w)};
                unsigned A1a[4] = {__float_as_uint(va2.x), __float_as_uint(va2.y),
                                   __float_as_uint(va2.z), __float_as_uint(va2.w)};
                unsigned A1b[4] = {__float_as_uint(va3.x), __float_as_uint(va3.y),
                                   __float_as_uint(va3.z), __float_as_uint(va3.w)};
                const float4* hb4 = (const float4*)(sStg + (t & 1) * STGB_F + w * 1024);
#pragma unroll
                for (int nt = 0; nt < 8; nt++) {
                    float4 bv = hb4[(nt * 8 + g) * 4 + tg];
                    unsigned b0[2] = {__float_as_uint(bv.x), __float_as_uint(bv.y)};
                    unsigned b1[2] = {__float_as_uint(bv.z), __float_as_uint(bv.w)};
                    mma_tf32(acc[0][nt], A0a, b0);
                    mma_tf32(acc[1][nt], A0b, b0);
                    mma_tf32(acc[0][nt], A1a, b1);
                    mma_tf32(acc[1][nt], A1b, b1);
                }
            }
        } else {
            cpa_wait<0>();
        }

        // prefetch next step's xg slice (independent of h)
        if (s + 1 < S_) prefetch_xg(s + 1);

        // ---- cross-warp reduce: rbuf4[src*512 + f*32 + lane], conflict-free ----
        __syncthreads();
#pragma unroll
        for (int mt = 0; mt < 2; mt++)
#pragma unroll
            for (int nt = 0; nt < 8; nt++)
                rbuf4[w * 512 + (mt * 8 + nt) * 32 + lane] =
                    make_float4(acc[mt][nt][0], acc[mt][nt][1], acc[mt][nt][2], acc[mt][nt][3]);
        __syncthreads();
        float fin[2][4];
#pragma unroll
        for (int mt = 0; mt < 2; mt++)
#pragma unroll
            for (int j = 0; j < 4; j++) fin[mt][j] = 0.f;
#pragma unroll
        for (int src = 0; src < 8; src++) {
            float4 v0 = rbuf4[src * 512 + w * 32 + lane];
            float4 v1 = rbuf4[src * 512 + (8 + w) * 32 + lane];
            fin[0][0] += v0.x; fin[0][1] += v0.y; fin[0][2] += v0.z; fin[0][3] += v0.w;
            fin[1][0] += v1.x; fin[1][1] += v1.y; fin[1][2] += v1.z; fin[1][3] += v1.w;
        }

        // ---- pointwise: critical path = compute + hout store only ----
        const float* xb = sXg + (s & 1) * 2048;
        float cval[2], hval[2];
#pragma unroll
        for (int hh = 0; hh < 2; hh++) {
            int bb = w * 8 + tg * 2 + hh;
            float iv = fin[0][hh]     + xb[bb * 8 + g];
            float fv = fin[0][2 + hh] + xb[512 + bb * 8 + g];
            float gv = fin[1][hh]     + xb[1024 + bb * 8 + g];
            float ov = fin[1][2 + hh] + xb[1536 + bb * 8 + g];
            float cn = sigm(fv) * creg[hh] + sigm(iv) * tanhf(gv);
            float hn = sigm(ov) * tanhf(cn);
            bool m = s < lenr[hh];
            cval[hh] = m ? cn : creg[hh];
            hval[hh] = m ? hn : hreg[hh];
            creg[hh] = cval[hh];
            hreg[hh] = hval[hh];
            hout[bb * H_ + hoff] = __uint_as_float(f2tf(hval[hh]));
        }

        // ---- POST: publish progress as soon as critical writes are visible ----
        __syncthreads();
        if (tid == 0) {
            asm volatile("st.release.gpu.global.u32 [%0], %1;"
                         :: "l"((unsigned*)&g_flags[blockIdx.x * 32]),
                            "r"(tbase + (unsigned)s + 1) : "memory");
        }

        // ---- non-critical output writes, overlapped with straggler window ----
#pragma unroll
        for (int hh = 0; hh < 2; hh++) {
            int bb = w * 8 + tg * 2 + hh;
            float hf = hval[hh];
            if (layer == 0) g_h1[((size_t)s * 64 + bb) * H_ + u] = __uint_as_float(f2tf(hf));
            else            out[((size_t)bb * S_ + s) * H_ + u] = hf;
            if (s == S_ - 1) {
                out[OUT_CS + layer * LSTRIDE + bb * H_ + u] = cval[hh];
                out[OUT_HS + layer * LSTRIDE + bb * H_ + u] = hf;
            }
        }

        // ---- DRAIN: wait for all CTAs before next step's staging ----
        if (s < S_ - 1) {
            unsigned tgt = tbase + (unsigned)s + 1;
            if (tid < NCTA) {
                const unsigned* p = (const unsigned*)&g_flags[tid * 32];
                unsigned v;
                do {
                    asm volatile("ld.acquire.gpu.global.u32 %0, [%1];"
                                 : "=r"(v) : "l"(p) : "memory");
                } while (v < tgt);
            }
            __syncthreads();
        }
    }
}

// ---------------- launch ----------------
extern "C" void kernel_launch(void* const* d_in, const int* in_sizes, int n_in,
                              void* d_out, int out_size) {
    const int*   inputs  = (const int*)d_in[0];
    const int*   lengths = (const int*)d_in[1];
    const float* emb     = (const float*)d_in[3];
    const float* Wx      = (const float*)d_in[4];
    const float* Wh      = (const float*)d_in[5];
    const float* bias    = (const float*)d_in[6];
    float* out = (float*)d_out;

    cudaFuncSetAttribute(gemm_xg,   cudaFuncAttributeMaxDynamicSharedMemorySize, GEMM_SMEM);
    cudaFuncSetAttribute(lstm_pers, cudaFuncAttributeMaxDynamicSharedMemorySize, PS_SMEM);

    round_both<<<16384, 256>>>(Wx, Wh);
    embed_kernel<<<NROW, 256>>>(inputs, emb);

    for (int l = 0; l < 2; l++) {
        gemm_xg<<<dim3(32, 128), 256, GEMM_SMEM>>>(l, bias + l * G_);
        lstm_pers<<<NCTA, 256, PS_SMEM>>>(l, lengths, out);
    }
}